// round 1
// baseline (speedup 1.0000x reference)
#include <cuda_runtime.h>
#include <math.h>

// Problem dims (fixed by setup_inputs)
#define BB 8
#define LQ 1024
#define LK 8192
#define DD 256
#define DC 128
#define EPSF 1e-6f

// Scratch (device globals; no allocation allowed)
__device__ float d_G[DC * DC];            // Gram = W^T W  (64 KB)
__device__ float d_qc[BB * LQ * DC];      // q @ W_up       (4 MB)
__device__ float d_qsq[BB * LQ];
__device__ float d_kc[BB * LK * DC];      // dequantized compressed keys (32 MB)
__device__ float d_ksq[BB * LK];

// ---------------------------------------------------------------------------
// Kernel 1: G[c][c'] = sum_d W[d][c] * W[d][c']   (W row-major [256][128])
// ---------------------------------------------------------------------------
__global__ void gram_kernel(const float* __restrict__ W) {
    const int c = blockIdx.x;     // 0..127
    const int cp = threadIdx.x;   // 0..127
    float s = 0.f;
#pragma unroll 8
    for (int d = 0; d < DD; d++) {
        s += W[d * DC + c] * W[d * DC + cp];
    }
    d_G[c * DC + cp] = s;
}

// ---------------------------------------------------------------------------
// Kernel 2: q_c[row][c] = sum_d q[row][d] * W[d][c];  q_sq[row] = ||q_row||^2
// one block per row (B*Lq rows), 128 threads
// ---------------------------------------------------------------------------
__global__ __launch_bounds__(128) void qc_kernel(const float* __restrict__ q,
                                                 const float* __restrict__ W) {
    const int row = blockIdx.x;           // 0 .. B*LQ-1
    const int t = threadIdx.x;            // 0..127
    __shared__ float qrow[DD];
    __shared__ float red[4];
    const float v0 = q[row * DD + t];
    const float v1 = q[row * DD + 128 + t];
    qrow[t] = v0;
    qrow[t + 128] = v1;
    __syncthreads();
    float s = 0.f;
#pragma unroll 8
    for (int d = 0; d < DD; d++) {
        s += qrow[d] * W[d * DC + t];
    }
    d_qc[row * DC + t] = s;
    // q_sq reduction
    float e = v0 * v0 + v1 * v1;
#pragma unroll
    for (int off = 16; off > 0; off >>= 1)
        e += __shfl_down_sync(0xffffffffu, e, off);
    if ((t & 31) == 0) red[t >> 5] = e;
    __syncthreads();
    if (t == 0) d_qsq[row] = red[0] + red[1] + red[2] + red[3];
}

// ---------------------------------------------------------------------------
// Kernel 3: dequantize k_c and compute k_sq = k_c^T G k_c.
// Block = 512 threads = (c in [0,128), h in [0,4)). Each thread holds
// G[h*32 .. h*32+31][c] in registers; processes KSQ_ROWS rows per block.
// ---------------------------------------------------------------------------
#define KSQ_ROWS 64
__global__ __launch_bounds__(512) void kc_ksq_kernel(const int* __restrict__ kq,
                                                     const float* __restrict__ kscale,
                                                     const float* __restrict__ kzero) {
    const int tid = threadIdx.x;
    const int c = tid & 127;
    const int h = tid >> 7;                     // 0..3
    const int rowBase = blockIdx.x * KSQ_ROWS;  // global row index (b*LK + l)
    const int b = rowBase >> 13;                // LK = 8192 rows per batch

    float Greg[32];
#pragma unroll
    for (int j = 0; j < 32; j++)
        Greg[j] = d_G[(h * 32 + j) * DC + c];

    const float scale = kscale[b * DC + c];
    const float zero  = kzero [b * DC + c];

    __shared__ float kcs[DC];
    __shared__ float tpart[4][DC];
    __shared__ float red[4];

    for (int r = 0; r < KSQ_ROWS; r++) {
        const int row = rowBase + r;
        if (h == 0) {
            float v = scale * ((float)kq[row * DC + c] - zero);
            d_kc[row * DC + c] = v;
            kcs[c] = v;
        }
        __syncthreads();
        // partial t[c] over c' in [h*32, h*32+32)
        float s = 0.f;
        const float4* kv = (const float4*)&kcs[h * 32];
#pragma unroll
        for (int j4 = 0; j4 < 8; j4++) {
            float4 v = kv[j4];
            s += Greg[j4 * 4 + 0] * v.x;
            s += Greg[j4 * 4 + 1] * v.y;
            s += Greg[j4 * 4 + 2] * v.z;
            s += Greg[j4 * 4 + 3] * v.w;
        }
        tpart[h][c] = s;
        __syncthreads();
        if (h == 0) {
            float t = tpart[0][c] + tpart[1][c] + tpart[2][c] + tpart[3][c];
            float contrib = kcs[c] * t;
#pragma unroll
            for (int off = 16; off > 0; off >>= 1)
                contrib += __shfl_down_sync(0xffffffffu, contrib, off);
            if ((c & 31) == 0) red[c >> 5] = contrib;
        }
        __syncthreads();
        if (tid == 0) d_ksq[row] = red[0] + red[1] + red[2] + red[3];
        __syncthreads();
    }
}

// ---------------------------------------------------------------------------
// Kernel 4: main fused GEMM + epilogue.
// C[b,i,j] = q_c[b,i,:] . k_c[b,j,:]  (K = 128), then hyperbolic distance.
// 64x64 tile per block, 256 threads, 4x4 register tile per thread.
// ---------------------------------------------------------------------------
__global__ __launch_bounds__(256) void dist_kernel(const float* __restrict__ qsq,
                                                   const float* __restrict__ ksq,
                                                   float* __restrict__ out) {
    const int b = blockIdx.z;
    const int i0 = blockIdx.y * 64;
    const int j0 = blockIdx.x * 64;

    const float* A = d_qc + ((size_t)b * LQ + i0) * DC;   // 64 rows x 128
    const float* Bp = d_kc + ((size_t)b * LK + j0) * DC;  // 64 rows x 128

    __shared__ float As[16][68];
    __shared__ float Bs[16][68];

    const int tid = threadIdx.x;
    const int tx = tid & 15;       // 0..15 -> j
    const int ty = tid >> 4;       // 0..15 -> i
    const int lrow = tid >> 2;     // 0..63   (load row)
    const int lk4 = (tid & 3) << 2;  // 0,4,8,12 (load k offset)

    float acc[4][4];
#pragma unroll
    for (int r = 0; r < 4; r++)
#pragma unroll
        for (int cc = 0; cc < 4; cc++) acc[r][cc] = 0.f;

#pragma unroll 1
    for (int kt = 0; kt < DC; kt += 16) {
        float4 a4 = *(const float4*)(A + lrow * DC + kt + lk4);
        float4 b4 = *(const float4*)(Bp + lrow * DC + kt + lk4);
        __syncthreads();   // previous chunk fully consumed
        As[lk4 + 0][lrow] = a4.x;
        As[lk4 + 1][lrow] = a4.y;
        As[lk4 + 2][lrow] = a4.z;
        As[lk4 + 3][lrow] = a4.w;
        Bs[lk4 + 0][lrow] = b4.x;
        Bs[lk4 + 1][lrow] = b4.y;
        Bs[lk4 + 2][lrow] = b4.z;
        Bs[lk4 + 3][lrow] = b4.w;
        __syncthreads();
#pragma unroll
        for (int k = 0; k < 16; k++) {
            float4 av = *(const float4*)&As[k][ty << 2];
            float4 bv = *(const float4*)&Bs[k][tx << 2];
            acc[0][0] += av.x * bv.x; acc[0][1] += av.x * bv.y;
            acc[0][2] += av.x * bv.z; acc[0][3] += av.x * bv.w;
            acc[1][0] += av.y * bv.x; acc[1][1] += av.y * bv.y;
            acc[1][2] += av.y * bv.z; acc[1][3] += av.y * bv.w;
            acc[2][0] += av.z * bv.x; acc[2][1] += av.z * bv.y;
            acc[2][2] += av.z * bv.z; acc[2][3] += av.z * bv.w;
            acc[3][0] += av.w * bv.x; acc[3][1] += av.w * bv.y;
            acc[3][2] += av.w * bv.z; acc[3][3] += av.w * bv.w;
        }
    }

    // Epilogue: hyperbolic distance
    const int i = i0 + (ty << 2);
    const int j = j0 + (tx << 2);
    float qs[4], ks[4];
#pragma unroll
    for (int r = 0; r < 4; r++) qs[r] = qsq[b * LQ + i + r];
#pragma unroll
    for (int cc = 0; cc < 4; cc++) ks[cc] = ksq[b * LK + j + cc];

#pragma unroll
    for (int r = 0; r < 4; r++) {
        const float dq = 1.0f - fminf(qs[r], 1.0f - EPSF);
        float4 o;
        float vals[4];
#pragma unroll
        for (int cc = 0; cc < 4; cc++) {
            float diff = fmaxf(qs[r] + ks[cc] - 2.0f * acc[r][cc], 0.0f);
            float dk = 1.0f - fminf(ks[cc], 1.0f - EPSF);
            float denom = dq * dk + EPSF;
            float x = 1.0f + 2.0f * diff / denom;
            vals[cc] = acoshf(x);
        }
        o.x = vals[0]; o.y = vals[1]; o.z = vals[2]; o.w = vals[3];
        *(float4*)(out + (((size_t)b * LQ + i + r) * LK) + j) = o;
    }
}

// ---------------------------------------------------------------------------
extern "C" void kernel_launch(void* const* d_in, const int* in_sizes, int n_in,
                              void* d_out, int out_size) {
    const float* q      = (const float*)d_in[0];   // (8,1024,256) f32
    const int*   k_q    = (const int*)  d_in[1];   // (8,8192,128) i32
    const float* k_scale= (const float*)d_in[2];   // (8,1,128)
    const float* k_zero = (const float*)d_in[3];   // (8,1,128)
    const float* W_up   = (const float*)d_in[4];   // (256,128)
    float* out = (float*)d_out;                    // (8,1024,8192)

    gram_kernel<<<DC, DC>>>(W_up);
    qc_kernel<<<BB * LQ, 128>>>(q, W_up);
    kc_ksq_kernel<<<(BB * LK) / KSQ_ROWS, 512>>>(k_q, k_scale, k_zero);

    float* qsq_ptr; float* ksq_ptr;
    cudaGetSymbolAddress((void**)&qsq_ptr, d_qsq);
    cudaGetSymbolAddress((void**)&ksq_ptr, d_ksq);

    dim3 grid(LK / 64, LQ / 64, BB);
    dist_kernel<<<grid, 256>>>(qsq_ptr, ksq_ptr, out);
}

// round 4
// speedup vs baseline: 1.9367x; 1.9367x over previous
#include <cuda_runtime.h>
#include <cuda_bf16.h>
#include <math.h>
#include <stdint.h>

#define BB 8
#define LQ 1024
#define LK 8192
#define DD 256
#define DC 128
#define EPSF 1e-6f

// Scratch (device globals; no allocation allowed)
__device__ float          d_G[DC * DC];          // Gram = W^T W (fp32, 64 KB)
__device__ __nv_bfloat16  d_qcb[BB * LQ * DC];   // q @ W_up, bf16 (2 MB)
__device__ __nv_bfloat16  d_kcb[BB * LK * DC];   // dequantized keys, bf16 (16 MB)
__device__ float          d_qsq[BB * LQ];
__device__ float          d_ksq[BB * LK];

// ---------------------------------------------------------------------------
// Kernel 1: G[c][c'] = sum_d W[d][c] * W[d][c']
// ---------------------------------------------------------------------------
__global__ void gram_kernel(const float* __restrict__ W) {
    const int c = blockIdx.x;
    const int cp = threadIdx.x;
    float s = 0.f;
#pragma unroll 8
    for (int d = 0; d < DD; d++)
        s += W[d * DC + c] * W[d * DC + cp];
    d_G[c * DC + cp] = s;
}

// ---------------------------------------------------------------------------
// Kernel 2: q_c = q @ W_up  ->  bf16.  16 rows per block, W staged in SMEM.
// ---------------------------------------------------------------------------
__global__ __launch_bounds__(128) void qc_kernel(const float* __restrict__ q,
                                                 const float* __restrict__ W) {
    const int c = threadIdx.x;
    const int row0 = blockIdx.x * 16;
    __shared__ float Ws[64][DC];   // 32 KB
    __shared__ float qs[16][64];   // 4 KB
    float acc[16];
#pragma unroll
    for (int r = 0; r < 16; r++) acc[r] = 0.f;

    for (int dch = 0; dch < 4; dch++) {
        __syncthreads();
#pragma unroll 8
        for (int r = 0; r < 64; r++)
            Ws[r][c] = W[(dch * 64 + r) * DC + c];
#pragma unroll
        for (int i = 0; i < 8; i++) {
            int idx = i * 128 + c;          // 0..1023
            int r = idx >> 6;               // 0..15
            int d = idx & 63;
            qs[r][d] = q[(row0 + r) * DD + dch * 64 + d];
        }
        __syncthreads();
#pragma unroll 8
        for (int d = 0; d < 64; d++) {
            float w = Ws[d][c];
#pragma unroll
            for (int r = 0; r < 16; r++)
                acc[r] += qs[r][d] * w;
        }
    }
#pragma unroll
    for (int r = 0; r < 16; r++)
        d_qcb[(row0 + r) * DC + c] = __float2bfloat16(acc[r]);
}

// ---------------------------------------------------------------------------
// Kernel 2b: q_sq (exact fp32 from original q). One warp per row.
// ---------------------------------------------------------------------------
__global__ __launch_bounds__(256) void qsq_kernel(const float* __restrict__ q) {
    const int warp = threadIdx.x >> 5;
    const int lane = threadIdx.x & 31;
    const int row = blockIdx.x * 8 + warp;
    const float4* qr = (const float4*)(q + row * DD);
    float s = 0.f;
#pragma unroll
    for (int i = 0; i < 2; i++) {
        float4 v = qr[lane + i * 32];
        s += v.x * v.x + v.y * v.y + v.z * v.z + v.w * v.w;
    }
#pragma unroll
    for (int off = 16; off > 0; off >>= 1)
        s += __shfl_down_sync(0xffffffffu, s, off);
    if (lane == 0) d_qsq[row] = s;
}

// ---------------------------------------------------------------------------
// Kernel 3: dequant k_c -> bf16, and k_sq = k_c^T G k_c.
// 512 threads = (c in [0,128), h in [0,4)). Thread holds G[h*32..+32)[c]
// in registers. 4 rows in flight per barrier phase, 64 rows per block.
// ---------------------------------------------------------------------------
#define KR 64
__global__ __launch_bounds__(512) void kc_ksq_kernel(const int* __restrict__ kq,
                                                     const float* __restrict__ kscale,
                                                     const float* __restrict__ kzero) {
    const int tid = threadIdx.x;
    const int c = tid & 127;
    const int h = tid >> 7;                  // 0..3
    const int lane = tid & 31;
    const int base = blockIdx.x * KR;
    const int b = base >> 13;                // LK = 8192 rows/batch

    float Greg[32];
#pragma unroll
    for (int j = 0; j < 32; j++)
        Greg[j] = d_G[(h * 32 + j) * DC + c];

    const float scale = kscale[b * DC + c];
    const float zero  = kzero [b * DC + c];

    __shared__ float kcs[4][DC];
    __shared__ float tpart[4][4][DC];  // [h][s][c]
    __shared__ float red[4][4];

    for (int phase = 0; phase < KR / 4; phase++) {
        const int row = base + phase * 4 + h;   // thread-group h owns row slot h
        float v = scale * ((float)kq[row * DC + c] - zero);
        d_kcb[row * DC + c] = __float2bfloat16(v);
        kcs[h][c] = v;
        __syncthreads();

        float a0 = 0.f, a1 = 0.f, a2 = 0.f, a3 = 0.f;
        const float4* k0 = (const float4*)&kcs[0][h * 32];
        const float4* k1 = (const float4*)&kcs[1][h * 32];
        const float4* k2 = (const float4*)&kcs[2][h * 32];
        const float4* k3 = (const float4*)&kcs[3][h * 32];
#pragma unroll
        for (int j4 = 0; j4 < 8; j4++) {
            float g0 = Greg[j4 * 4 + 0], g1 = Greg[j4 * 4 + 1];
            float g2 = Greg[j4 * 4 + 2], g3 = Greg[j4 * 4 + 3];
            float4 v0 = k0[j4], v1 = k1[j4], v2 = k2[j4], v3 = k3[j4];
            a0 += g0 * v0.x + g1 * v0.y + g2 * v0.z + g3 * v0.w;
            a1 += g0 * v1.x + g1 * v1.y + g2 * v1.z + g3 * v1.w;
            a2 += g0 * v2.x + g1 * v2.y + g2 * v2.z + g3 * v2.w;
            a3 += g0 * v3.x + g1 * v3.y + g2 * v3.z + g3 * v3.w;
        }
        tpart[h][0][c] = a0;
        tpart[h][1][c] = a1;
        tpart[h][2][c] = a2;
        tpart[h][3][c] = a3;
        __syncthreads();

        float t = tpart[0][h][c] + tpart[1][h][c] + tpart[2][h][c] + tpart[3][h][c];
        float contrib = kcs[h][c] * t;
#pragma unroll
        for (int off = 16; off > 0; off >>= 1)
            contrib += __shfl_down_sync(0xffffffffu, contrib, off);
        if (lane == 0) red[h][(c >> 5)] = contrib;
        __syncthreads();
        if (c == 0)
            d_ksq[row] = red[h][0] + red[h][1] + red[h][2] + red[h][3];
        __syncthreads();
    }
}

// ---------------------------------------------------------------------------
// Kernel 4: main fused bf16 tensor-core GEMM + hyperbolic-distance epilogue.
// 128x128 block tile, 256 threads (8 warps, 2x4), warp tile 64x32,
// mma.sync.m16n8k16 bf16 -> fp32.
// ---------------------------------------------------------------------------
__device__ __forceinline__ void ldsm_x4(uint32_t& r0, uint32_t& r1,
                                        uint32_t& r2, uint32_t& r3,
                                        const void* p) {
    uint32_t a = (uint32_t)__cvta_generic_to_shared(p);
    asm volatile("ldmatrix.sync.aligned.m8n8.x4.shared.b16 {%0,%1,%2,%3}, [%4];\n"
                 : "=r"(r0), "=r"(r1), "=r"(r2), "=r"(r3) : "r"(a));
}

__device__ __forceinline__ void mma_bf16(float* d, const uint32_t* a, const uint32_t* b) {
    asm volatile(
        "mma.sync.aligned.m16n8k16.row.col.f32.bf16.bf16.f32 "
        "{%0,%1,%2,%3}, {%4,%5,%6,%7}, {%8,%9}, {%0,%1,%2,%3};\n"
        : "+f"(d[0]), "+f"(d[1]), "+f"(d[2]), "+f"(d[3])
        : "r"(a[0]), "r"(a[1]), "r"(a[2]), "r"(a[3]), "r"(b[0]), "r"(b[1]));
}

#define SPAD 8
__global__ __launch_bounds__(256) void dist_kernel(const float* __restrict__ qsq,
                                                   const float* __restrict__ ksq,
                                                   float* __restrict__ out) {
    __shared__ __nv_bfloat16 As[128][64 + SPAD];
    __shared__ __nv_bfloat16 Bs[128][64 + SPAD];

    const int b = blockIdx.z;
    const int i0 = blockIdx.y * 128;
    const int j0 = blockIdx.x * 128;
    const int tid = threadIdx.x;
    const int warp = tid >> 5;
    const int lane = tid & 31;
    const int m0 = (warp & 1) * 64;
    const int n0 = (warp >> 1) * 32;

    const __nv_bfloat16* Ag = d_qcb + ((size_t)b * LQ + i0) * DC;
    const __nv_bfloat16* Bg = d_kcb + ((size_t)b * LK + j0) * DC;

    float acc[4][4][4];
#pragma unroll
    for (int mt = 0; mt < 4; mt++)
#pragma unroll
        for (int nt = 0; nt < 4; nt++)
#pragma unroll
            for (int e = 0; e < 4; e++) acc[mt][nt][e] = 0.f;

#pragma unroll
    for (int chunk = 0; chunk < 2; chunk++) {
        __syncthreads();
#pragma unroll
        for (int p = 0; p < 4; p++) {
            int idx = tid + p * 256;      // 0..1023
            int r = idx >> 3;             // 0..127
            int seg = idx & 7;            // 16B segment
            *(uint4*)&As[r][seg * 8] = *(const uint4*)&Ag[r * DC + chunk * 64 + seg * 8];
            *(uint4*)&Bs[r][seg * 8] = *(const uint4*)&Bg[r * DC + chunk * 64 + seg * 8];
        }
        __syncthreads();

#pragma unroll
        for (int ks = 0; ks < 4; ks++) {
            uint32_t a[4][4];
            uint32_t bb[4][2];
            const int arow = m0 + (lane & 7) + ((lane >> 3) & 1) * 8;
            const int acol = ks * 16 + (lane >> 4) * 8;
#pragma unroll
            for (int mt = 0; mt < 4; mt++)
                ldsm_x4(a[mt][0], a[mt][1], a[mt][2], a[mt][3], &As[arow + mt * 16][acol]);
            const int brow = n0 + (lane & 7) + (lane >> 4) * 8;
            const int bcol = ks * 16 + ((lane >> 3) & 1) * 8;
#pragma unroll
            for (int ntp = 0; ntp < 2; ntp++) {
                uint32_t r0, r1, r2, r3;
                ldsm_x4(r0, r1, r2, r3, &Bs[brow + ntp * 16][bcol]);
                bb[ntp * 2][0] = r0; bb[ntp * 2][1] = r1;
                bb[ntp * 2 + 1][0] = r2; bb[ntp * 2 + 1][1] = r3;
            }
#pragma unroll
            for (int mt = 0; mt < 4; mt++)
#pragma unroll
                for (int nt = 0; nt < 4; nt++)
                    mma_bf16(acc[mt][nt], a[mt], bb[nt]);
        }
    }

    // ---------------- epilogue ----------------
    const int rb = i0 + m0 + (lane >> 2);          // global i for h=0, mt=0
    const int cb = j0 + n0 + 2 * (lane & 3);       // global j for nt=0

    float qrow[4][2];
#pragma unroll
    for (int mt = 0; mt < 4; mt++) {
        qrow[mt][0] = qsq[b * LQ + rb + mt * 16];
        qrow[mt][1] = qsq[b * LQ + rb + mt * 16 + 8];
    }
    float2 kcol[4];
    float dk[4][2];
#pragma unroll
    for (int nt = 0; nt < 4; nt++) {
        kcol[nt] = *(const float2*)&ksq[b * LK + cb + nt * 8];
        dk[nt][0] = 1.0f - fminf(kcol[nt].x, 1.0f - EPSF);
        dk[nt][1] = 1.0f - fminf(kcol[nt].y, 1.0f - EPSF);
    }

#pragma unroll
    for (int mt = 0; mt < 4; mt++) {
#pragma unroll
        for (int hh = 0; hh < 2; hh++) {
            const int row = rb + mt * 16 + hh * 8;
            const float q2 = qrow[mt][hh];
            const float dq = 1.0f - fminf(q2, 1.0f - EPSF);
            float* orow = out + ((size_t)b * LQ + row) * LK;
#pragma unroll
            for (int nt = 0; nt < 4; nt++) {
                float v0 = acc[mt][nt][hh * 2 + 0];
                float v1 = acc[mt][nt][hh * 2 + 1];
                float diff0 = fmaxf(q2 + kcol[nt].x - 2.0f * v0, 0.0f);
                float diff1 = fmaxf(q2 + kcol[nt].y - 2.0f * v1, 0.0f);
                float den0 = dq * dk[nt][0] + EPSF;
                float den1 = dq * dk[nt][1] + EPSF;
                float x0 = 1.0f + 2.0f * diff0 / den0;
                float x1 = 1.0f + 2.0f * diff1 / den1;
                float2 o;
                o.x = acoshf(x0);
                o.y = acoshf(x1);
                *(float2*)&orow[cb + nt * 8] = o;
            }
        }
    }
}

// ---------------------------------------------------------------------------
extern "C" void kernel_launch(void* const* d_in, const int* in_sizes, int n_in,
                              void* d_out, int out_size) {
    const float* q       = (const float*)d_in[0];   // (8,1024,256) f32
    const int*   k_q     = (const int*)  d_in[1];   // (8,8192,128) i32
    const float* k_scale = (const float*)d_in[2];   // (8,1,128)
    const float* k_zero  = (const float*)d_in[3];   // (8,1,128)
    const float* W_up    = (const float*)d_in[4];   // (256,128)
    float* out = (float*)d_out;                     // (8,1024,8192)

    gram_kernel<<<DC, DC>>>(W_up);
    qc_kernel<<<(BB * LQ) / 16, 128>>>(q, W_up);
    qsq_kernel<<<(BB * LQ) / 8, 256>>>(q);
    kc_ksq_kernel<<<(BB * LK) / KR, 512>>>(k_q, k_scale, k_zero);

    float* qsq_ptr; float* ksq_ptr;
    cudaGetSymbolAddress((void**)&qsq_ptr, d_qsq);
    cudaGetSymbolAddress((void**)&ksq_ptr, d_ksq);

    dim3 grid(LK / 128, LQ / 128, BB);
    dist_kernel<<<grid, 256>>>(qsq_ptr, ksq_ptr, out);
}

// round 9
// speedup vs baseline: 3.0719x; 1.5861x over previous
#include <cuda_runtime.h>
#include <cuda_bf16.h>
#include <math.h>
#include <stdint.h>

#define BB 8
#define LQ 1024
#define LK 8192
#define DD 256
#define DC 128
#define EPSF 1e-6f

// Scratch (device globals; no allocation allowed)
__device__ __nv_bfloat16  d_Gb[DC * DC];         // Gram = W^T W, bf16 (32 KB)
__device__ __nv_bfloat16  d_qcb[BB * LQ * DC];   // q @ W_up, bf16 (2 MB)
__device__ __nv_bfloat16  d_kcb[BB * LK * DC];   // dequantized keys, bf16 (16 MB)
__device__ float          d_qsq[BB * LQ];
__device__ float          d_ksq[BB * LK];

// ---------------------------------------------------------------------------
// fast-math helpers (approx MUFU ops, explicit so we don't depend on flags)
// ---------------------------------------------------------------------------
__device__ __forceinline__ float fast_rcp(float x) {
    float r; asm("rcp.approx.f32 %0, %1;" : "=f"(r) : "f"(x)); return r;
}
__device__ __forceinline__ float fast_sqrt(float x) {
    float r; asm("sqrt.approx.f32 %0, %1;" : "=f"(r) : "f"(x)); return r;
}
__device__ __forceinline__ float fast_lg2(float x) {
    float r; asm("lg2.approx.f32 %0, %1;" : "=f"(r) : "f"(x)); return r;
}
// acosh(x) = ln(x + sqrt(x^2-1)), x >= 1
__device__ __forceinline__ float fast_acosh(float x) {
    float t = fast_sqrt(__fmaf_rn(x, x, -1.0f));
    return fast_lg2(x + t) * 0.69314718055994531f;
}

// ---------------------------------------------------------------------------
// Kernel 1: G[c][c'] = sum_d W[d][c] * W[d][c']  -> bf16
// ---------------------------------------------------------------------------
__global__ void gram_kernel(const float* __restrict__ W) {
    const int c = blockIdx.x;
    const int cp = threadIdx.x;
    float s = 0.f;
#pragma unroll 8
    for (int d = 0; d < DD; d++)
        s += W[d * DC + c] * W[d * DC + cp];
    d_Gb[c * DC + cp] = __float2bfloat16(s);
}

// ---------------------------------------------------------------------------
// Kernel 2: q_c = q @ W_up  ->  bf16.  16 rows per block, W staged in SMEM.
// ---------------------------------------------------------------------------
__global__ __launch_bounds__(128) void qc_kernel(const float* __restrict__ q,
                                                 const float* __restrict__ W) {
    const int c = threadIdx.x;
    const int row0 = blockIdx.x * 16;
    __shared__ float Ws[64][DC];   // 32 KB
    __shared__ float qs[16][64];   // 4 KB
    float acc[16];
#pragma unroll
    for (int r = 0; r < 16; r++) acc[r] = 0.f;

    for (int dch = 0; dch < 4; dch++) {
        __syncthreads();
#pragma unroll 8
        for (int r = 0; r < 64; r++)
            Ws[r][c] = W[(dch * 64 + r) * DC + c];
#pragma unroll
        for (int i = 0; i < 8; i++) {
            int idx = i * 128 + c;
            int r = idx >> 6;
            int d = idx & 63;
            qs[r][d] = q[(row0 + r) * DD + dch * 64 + d];
        }
        __syncthreads();
#pragma unroll 8
        for (int d = 0; d < 64; d++) {
            float w = Ws[d][c];
#pragma unroll
            for (int r = 0; r < 16; r++)
                acc[r] += qs[r][d] * w;
        }
    }
#pragma unroll
    for (int r = 0; r < 16; r++)
        d_qcb[(row0 + r) * DC + c] = __float2bfloat16(acc[r]);
}

// ---------------------------------------------------------------------------
// Kernel 2b: q_sq (exact fp32 from original q). One warp per row.
// ---------------------------------------------------------------------------
__global__ __launch_bounds__(256) void qsq_kernel(const float* __restrict__ q) {
    const int warp = threadIdx.x >> 5;
    const int lane = threadIdx.x & 31;
    const int row = blockIdx.x * 8 + warp;
    const float4* qr = (const float4*)(q + row * DD);
    float s = 0.f;
#pragma unroll
    for (int i = 0; i < 2; i++) {
        float4 v = qr[lane + i * 32];
        s += v.x * v.x + v.y * v.y + v.z * v.z + v.w * v.w;
    }
#pragma unroll
    for (int off = 16; off > 0; off >>= 1)
        s += __shfl_down_sync(0xffffffffu, s, off);
    if (lane == 0) d_qsq[row] = s;
}

// ---------------------------------------------------------------------------
// MMA helpers (shared by ksq_kernel and dist_kernel)
// ---------------------------------------------------------------------------
__device__ __forceinline__ void ldsm_x4(uint32_t& r0, uint32_t& r1,
                                        uint32_t& r2, uint32_t& r3,
                                        const void* p) {
    uint32_t a = (uint32_t)__cvta_generic_to_shared(p);
    asm volatile("ldmatrix.sync.aligned.m8n8.x4.shared.b16 {%0,%1,%2,%3}, [%4];\n"
                 : "=r"(r0), "=r"(r1), "=r"(r2), "=r"(r3) : "r"(a));
}

__device__ __forceinline__ void mma_bf16(float* d, const uint32_t* a, const uint32_t* b) {
    asm volatile(
        "mma.sync.aligned.m16n8k16.row.col.f32.bf16.bf16.f32 "
        "{%0,%1,%2,%3}, {%4,%5,%6,%7}, {%8,%9}, {%0,%1,%2,%3};\n"
        : "+f"(d[0]), "+f"(d[1]), "+f"(d[2]), "+f"(d[3])
        : "r"(a[0]), "r"(a[1]), "r"(a[2]), "r"(a[3]), "r"(b[0]), "r"(b[1]));
}

// ---------------------------------------------------------------------------
// Kernel 3: fused dequant + k_sq via tensor cores.
// Per block: 128 rows of one batch.
//   - dequant k_q int32 -> bf16 kc, write through to d_kcb and smem tile
//   - T = kc @ G  (M=128, N=128, K=128; G symmetric so col-major B tile = G rows)
//   - k_sq[row] = sum_c kc[row][c] * T[row][c]   (smem reduction)
// 256 threads, 8 warps, warp tile 64x32 (same fragment mapping as dist_kernel).
// ---------------------------------------------------------------------------
__global__ __launch_bounds__(256) void ksq_kernel(const int* __restrict__ kq,
                                                  const float* __restrict__ kscale,
                                                  const float* __restrict__ kzero) {
    __shared__ __nv_bfloat16 As[128][64 + 8];   // 18 KB
    __shared__ __nv_bfloat16 Gs[128][64 + 8];   // 18 KB
    __shared__ float part[128][17];             // 8.5 KB

    const int tid = threadIdx.x;
    const int warp = tid >> 5;
    const int lane = tid & 31;
    const int rowBase = blockIdx.x * 128;       // global row (b*LK + l)
    const int b = rowBase >> 13;                // LK = 8192 rows per batch
    const int m0 = (warp & 1) * 64;
    const int n0 = (warp >> 1) * 32;

    float acc[4][4][4];
#pragma unroll
    for (int mt = 0; mt < 4; mt++)
#pragma unroll
        for (int nt = 0; nt < 4; nt++)
#pragma unroll
            for (int e = 0; e < 4; e++) acc[mt][nt][e] = 0.f;

#pragma unroll
    for (int chunk = 0; chunk < 2; chunk++) {
        __syncthreads();
        // --- dequant load: 128 rows x 64 cols of k_q -> bf16 smem + global ---
#pragma unroll
        for (int p = 0; p < 8; p++) {
            int id = p * 256 + tid;            // 0..2047
            int r = id >> 4;                    // 0..127
            int seg = id & 15;                  // int4 index in the 64-col slab
            const int col = chunk * 64 + seg * 4;
            const int grow = rowBase + r;
            int4 iv = *(const int4*)&kq[grow * DC + col];
            float s0 = kscale[b * DC + col + 0], z0 = kzero[b * DC + col + 0];
            float s1 = kscale[b * DC + col + 1], z1 = kzero[b * DC + col + 1];
            float s2 = kscale[b * DC + col + 2], z2 = kzero[b * DC + col + 2];
            float s3 = kscale[b * DC + col + 3], z3 = kzero[b * DC + col + 3];
            __nv_bfloat162 h0, h1;
            h0.x = __float2bfloat16(s0 * ((float)iv.x - z0));
            h0.y = __float2bfloat16(s1 * ((float)iv.y - z1));
            h1.x = __float2bfloat16(s2 * ((float)iv.z - z2));
            h1.y = __float2bfloat16(s3 * ((float)iv.w - z3));
            uint2 packed = make_uint2(*(uint32_t*)&h0, *(uint32_t*)&h1);
            *(uint2*)&As[r][seg * 4] = packed;
            *(uint2*)&d_kcb[grow * DC + col] = packed;
        }
        // --- G tile: Gs[n][kk] = G[chunk*64+kk][n] = d_Gb[n*128 + chunk*64 + kk] ---
#pragma unroll
        for (int p = 0; p < 4; p++) {
            int id = p * 256 + tid;            // 0..1023
            int r = id >> 3;                    // 0..127 (n)
            int seg = id & 7;                   // 16B segment
            *(uint4*)&Gs[r][seg * 8] = *(const uint4*)&d_Gb[r * DC + chunk * 64 + seg * 8];
        }
        __syncthreads();

#pragma unroll
        for (int ks = 0; ks < 4; ks++) {
            uint32_t a[4][4];
            uint32_t bb[4][2];
            const int arow = m0 + (lane & 7) + ((lane >> 3) & 1) * 8;
            const int acol = ks * 16 + (lane >> 4) * 8;
#pragma unroll
            for (int mt = 0; mt < 4; mt++)
                ldsm_x4(a[mt][0], a[mt][1], a[mt][2], a[mt][3], &As[arow + mt * 16][acol]);
            const int brow = n0 + (lane & 7) + (lane >> 4) * 8;
            const int bcol = ks * 16 + ((lane >> 3) & 1) * 8;
#pragma unroll
            for (int ntp = 0; ntp < 2; ntp++) {
                uint32_t r0, r1, r2, r3;
                ldsm_x4(r0, r1, r2, r3, &Gs[brow + ntp * 16][bcol]);
                bb[ntp * 2][0] = r0; bb[ntp * 2][1] = r1;
                bb[ntp * 2 + 1][0] = r2; bb[ntp * 2 + 1][1] = r3;
            }
#pragma unroll
            for (int mt = 0; mt < 4; mt++)
#pragma unroll
                for (int nt = 0; nt < 4; nt++)
                    mma_bf16(acc[mt][nt], a[mt], bb[nt]);
        }
    }
    __syncthreads();

    // --- rowsum(kc * T): per-thread partials into conflict-free smem slots ---
    const int cidx = (warp >> 1) * 4 + (lane & 3);
#pragma unroll
    for (int mt = 0; mt < 4; mt++) {
#pragma unroll
        for (int hh = 0; hh < 2; hh++) {
            const int lrow = m0 + mt * 16 + hh * 8 + (lane >> 2);
            const int grow = rowBase + lrow;
            float p = 0.f;
#pragma unroll
            for (int nt = 0; nt < 4; nt++) {
                const int c0 = n0 + nt * 8 + 2 * (lane & 3);
                uint32_t kk = *(const uint32_t*)&d_kcb[grow * DC + c0];
                __nv_bfloat162 kv = *(__nv_bfloat162*)&kk;
                p += acc[mt][nt][hh * 2 + 0] * __bfloat162float(kv.x);
                p += acc[mt][nt][hh * 2 + 1] * __bfloat162float(kv.y);
            }
            part[lrow][cidx] = p;
        }
    }
    __syncthreads();
    if (tid < 128) {
        float s = 0.f;
#pragma unroll
        for (int j = 0; j < 16; j++) s += part[tid][j];
        d_ksq[rowBase + tid] = s;
    }
}

// ---------------------------------------------------------------------------
// Kernel 4: main fused bf16 tensor-core GEMM + hyperbolic-distance epilogue.
// 128x128 block tile, 256 threads (8 warps, 2x4), warp tile 64x32,
// mma.sync.m16n8k16 bf16 -> fp32.
// ---------------------------------------------------------------------------
#define SPAD 8
__global__ __launch_bounds__(256) void dist_kernel(const float* __restrict__ qsq,
                                                   const float* __restrict__ ksq,
                                                   float* __restrict__ out) {
    __shared__ __nv_bfloat16 As[128][64 + SPAD];
    __shared__ __nv_bfloat16 Bs[128][64 + SPAD];

    const int b = blockIdx.z;
    const int i0 = blockIdx.y * 128;
    const int j0 = blockIdx.x * 128;
    const int tid = threadIdx.x;
    const int warp = tid >> 5;
    const int lane = tid & 31;
    const int m0 = (warp & 1) * 64;
    const int n0 = (warp >> 1) * 32;

    const __nv_bfloat16* Ag = d_qcb + ((size_t)b * LQ + i0) * DC;
    const __nv_bfloat16* Bg = d_kcb + ((size_t)b * LK + j0) * DC;

    float acc[4][4][4];
#pragma unroll
    for (int mt = 0; mt < 4; mt++)
#pragma unroll
        for (int nt = 0; nt < 4; nt++)
#pragma unroll
            for (int e = 0; e < 4; e++) acc[mt][nt][e] = 0.f;

#pragma unroll
    for (int chunk = 0; chunk < 2; chunk++) {
        __syncthreads();
#pragma unroll
        for (int p = 0; p < 4; p++) {
            int idx = tid + p * 256;
            int r = idx >> 3;
            int seg = idx & 7;
            *(uint4*)&As[r][seg * 8] = *(const uint4*)&Ag[r * DC + chunk * 64 + seg * 8];
            *(uint4*)&Bs[r][seg * 8] = *(const uint4*)&Bg[r * DC + chunk * 64 + seg * 8];
        }
        __syncthreads();

#pragma unroll
        for (int ks = 0; ks < 4; ks++) {
            uint32_t a[4][4];
            uint32_t bb[4][2];
            const int arow = m0 + (lane & 7) + ((lane >> 3) & 1) * 8;
            const int acol = ks * 16 + (lane >> 4) * 8;
#pragma unroll
            for (int mt = 0; mt < 4; mt++)
                ldsm_x4(a[mt][0], a[mt][1], a[mt][2], a[mt][3], &As[arow + mt * 16][acol]);
            const int brow = n0 + (lane & 7) + (lane >> 4) * 8;
            const int bcol = ks * 16 + ((lane >> 3) & 1) * 8;
#pragma unroll
            for (int ntp = 0; ntp < 2; ntp++) {
                uint32_t r0, r1, r2, r3;
                ldsm_x4(r0, r1, r2, r3, &Bs[brow + ntp * 16][bcol]);
                bb[ntp * 2][0] = r0; bb[ntp * 2][1] = r1;
                bb[ntp * 2 + 1][0] = r2; bb[ntp * 2 + 1][1] = r3;
            }
#pragma unroll
            for (int mt = 0; mt < 4; mt++)
#pragma unroll
                for (int nt = 0; nt < 4; nt++)
                    mma_bf16(acc[mt][nt], a[mt], bb[nt]);
        }
    }

    // ---------------- epilogue ----------------
    const int rb = i0 + m0 + (lane >> 2);
    const int cb = j0 + n0 + 2 * (lane & 3);

    float qrow[4][2];
#pragma unroll
    for (int mt = 0; mt < 4; mt++) {
        qrow[mt][0] = qsq[b * LQ + rb + mt * 16];
        qrow[mt][1] = qsq[b * LQ + rb + mt * 16 + 8];
    }
    float2 kcol[4];
    float dk[4][2];
#pragma unroll
    for (int nt = 0; nt < 4; nt++) {
        kcol[nt] = *(const float2*)&ksq[b * LK + cb + nt * 8];
        dk[nt][0] = 1.0f - fminf(kcol[nt].x, 1.0f - EPSF);
        dk[nt][1] = 1.0f - fminf(kcol[nt].y, 1.0f - EPSF);
    }

#pragma unroll
    for (int mt = 0; mt < 4; mt++) {
#pragma unroll
        for (int hh = 0; hh < 2; hh++) {
            const int row = rb + mt * 16 + hh * 8;
            const float q2 = qrow[mt][hh];
            const float dq = 1.0f - fminf(q2, 1.0f - EPSF);
            float* orow = out + ((size_t)b * LQ + row) * LK;
#pragma unroll
            for (int nt = 0; nt < 4; nt++) {
                float v0 = acc[mt][nt][hh * 2 + 0];
                float v1 = acc[mt][nt][hh * 2 + 1];
                float diff0 = fmaxf(q2 + kcol[nt].x - 2.0f * v0, 0.0f);
                float diff1 = fmaxf(q2 + kcol[nt].y - 2.0f * v1, 0.0f);
                float r0 = fast_rcp(__fmaf_rn(dq, dk[nt][0], EPSF));
                float r1 = fast_rcp(__fmaf_rn(dq, dk[nt][1], EPSF));
                float x0 = __fmaf_rn(diff0 + diff0, r0, 1.0f);
                float x1 = __fmaf_rn(diff1 + diff1, r1, 1.0f);
                float2 o;
                o.x = fast_acosh(x0);
                o.y = fast_acosh(x1);
                *(float2*)&orow[cb + nt * 8] = o;
            }
        }
    }
}

// ---------------------------------------------------------------------------
extern "C" void kernel_launch(void* const* d_in, const int* in_sizes, int n_in,
                              void* d_out, int out_size) {
    const float* q       = (const float*)d_in[0];   // (8,1024,256) f32
    const int*   k_q     = (const int*)  d_in[1];   // (8,8192,128) i32
    const float* k_scale = (const float*)d_in[2];   // (8,1,128)
    const float* k_zero  = (const float*)d_in[3];   // (8,1,128)
    const float* W_up    = (const float*)d_in[4];   // (256,128)
    float* out = (float*)d_out;                     // (8,1024,8192)

    gram_kernel<<<DC, DC>>>(W_up);
    ksq_kernel<<<(BB * LK) / 128, 256>>>(k_q, k_scale, k_zero);
    qc_kernel<<<(BB * LQ) / 16, 128>>>(q, W_up);
    qsq_kernel<<<(BB * LQ) / 8, 256>>>(q);

    float* qsq_ptr; float* ksq_ptr;
    cudaGetSymbolAddress((void**)&qsq_ptr, d_qsq);
    cudaGetSymbolAddress((void**)&ksq_ptr, d_ksq);

    dim3 grid(LK / 128, LQ / 128, BB);
    dist_kernel<<<grid, 256>>>(qsq_ptr, ksq_ptr, out);
}